// round 9
// baseline (speedup 1.0000x reference)
#include <cuda_runtime.h>
#include <cstddef>

// ManyBodyVoxel: out[0, a, c=t*2+l, x, y, z] =
//   sum_n exp(coeff * || grid_l[x,y,z] - d[a,n]*mask_t[a,n] ||^2)
// Separable Gaussian -> rank-1 outer products of per-(atom,axis) exp rows.
// R9: R8 layout + even-padded type sections with zero records -> branchless
//     2-wide inner loop, no remainder, 6 LDS in flight; base record at slot 69.

#define NT 1024

typedef unsigned long long u64;

__device__ __forceinline__ u64 pk2(float v) {
    u64 r; asm("mov.b64 %0, {%1, %2};" : "=l"(r) : "f"(v), "f"(v)); return r;
}
__device__ __forceinline__ u64 fma2(u64 a, u64 b, u64 c) {
    u64 d; asm("fma.rn.f32x2 %0, %1, %2, %3;" : "=l"(d) : "l"(a), "l"(b), "l"(c)); return d;
}
__device__ __forceinline__ u64 mul2(u64 a, u64 b) {
    u64 d; asm("mul.rn.f32x2 %0, %1, %2;" : "=l"(d) : "l"(a), "l"(b)); return d;
}

__global__ __launch_bounds__(NT, 2)
void mbv_kernel(const float* __restrict__ dist,   // (1,128,64,3) fp32
                const float* __restrict__ sigma,  // (1,) fp32
                const int*   __restrict__ anum,   // (128,64) int64 or int32 (auto-detect)
                float* __restrict__ out)          // (1,128,10,16,16,16) fp32
{
    const int a   = blockIdx.x >> 1;
    const int l   = blockIdx.x & 1;   // 0: L=8, 1: L=12
    const int tid = threadIdx.x;
    const int zq  = tid & 3;          // z quarter: [zq*4, zq*4+4)
    const int y   = (tid >> 2) & 15;
    const int x   = (tid >> 6) & 15;

    // Record (slot): 64 floats = 256B. x @ +0, y @ +64B, z @ +128B, pad.
    // Slots 0..nslots-1: padded type-major sections (pad slot = all-zero record).
    // Slot 69 (fixed): base record (d = 0).
    __shared__ __align__(16) float tab[70 * 64];
    __shared__ float dsm[192];
    __shared__ short ord[70];         // slot -> atom index, or -1 for pad
    __shared__ int   startc[5];
    __shared__ int   cntc[5];
    __shared__ int   cpadc[5];
    __shared__ int   nslots;

    const float s  = sigma[0];
    const float cf = -0.5f / (s * s);

    // ---- Phase 0: warp0 classifies (ballot compaction, even-padded sections);
    //      threads 32..223 stage dist ----
    if (tid < 32) {
        int4 p = ((const int4*)anum)[tid];            // probe row 0 (dtype)
        int4 q = ((const int4*)anum)[a * 32 + tid];   // int64 view
        int2 r = ((const int2*)anum)[a * 32 + tid];   // int32 view
        bool i32 = __any_sync(0xffffffffu, (p.y | p.w) != 0);
        int z0 = i32 ? r.x : q.x;
        int z1 = i32 ? r.y : q.z;
        unsigned lt = (1u << tid) - 1u;
        const int ZT[5] = {1, 6, 7, 8, 16};
        int base = 0;
        #pragma unroll
        for (int t = 0; t < 5; t++) {
            unsigned m0 = __ballot_sync(0xffffffffu, z0 == ZT[t]);
            unsigned m1 = __ballot_sync(0xffffffffu, z1 == ZT[t]);
            int c0 = __popc(m0), c = c0 + __popc(m1);
            int cp = (c + 1) & ~1;                    // pad to even
            if (z0 == ZT[t]) ord[base + __popc(m0 & lt)]      = (short)(2 * tid);
            if (z1 == ZT[t]) ord[base + c0 + __popc(m1 & lt)] = (short)(2 * tid + 1);
            if (tid == 0) {
                startc[t] = base; cntc[t] = c; cpadc[t] = cp;
                if (cp != c) ord[base + c] = (short)-1;   // pad slot
            }
            base += cp;
        }
        if (tid == 0) nslots = base;
    } else if (tid < 224) {
        dsm[tid - 32] = dist[a * 192 + (tid - 32)];
    }

    __syncthreads();

    // ---- Phase 1: exp tables (this CTA's l) into padded slots; base at 69 ----
    {
        const int ns = nslots;
        if (tid < 6 * (ns + 1)) {             // unit = (slot, ax, jhalf)
            int slot = tid / 6;
            int rem  = tid - slot * 6;
            int ax   = rem >> 1;
            int jh   = rem & 1;
            int isbase = (slot == ns);
            int recid  = isbase ? 69 : slot;
            int an_i   = isbase ? 64 : (int)ord[slot];
            float* dst = &tab[recid * 64 + ax * 16 + jh * 8];
            if (an_i < 0) {                   // pad slot: all-zero record
                #pragma unroll
                for (int j = 0; j < 8; j++) dst[j] = 0.0f;
            } else {
                float dv   = (an_i == 64) ? 0.0f : dsm[an_i * 3 + ax];
                float Lp   = l ? 12.0f : 8.0f;
                float half = 0.5f * Lp;
                float step = Lp * (1.0f / 15.0f);
                float bse  = -half - dv + step * (float)(jh * 8);
                #pragma unroll
                for (int j = 0; j < 8; j++) {
                    float uu = bse + step * (float)j;
                    dst[j] = __expf(cf * uu * uu);
                }
            }
        }
    }

    __syncthreads();

    // ---- Phase 2: consumer. Thread owns 4 voxels z in [zq*4, zq*4+4) of (x,y) ----
    const char* tb = reinterpret_cast<const char*>(tab);
    const int offx = x * 4;
    const int offy = 64 + y * 4;
    const int offz = 128 + zq * 16;

    const char* br = tb + 69 * 256;   // base record
    const float bxy = *(const float*)(br + offx) * *(const float*)(br + offy);
    const ulonglong2 bq = *(const ulonglong2*)(br + offz);

    // out offset: (a*10 + t*2 + l)*4096 + x*256 + y*16 + zq*4  (floats)
    char* op = reinterpret_cast<char*>(out)
             + ((((size_t)(a * 10 + l)) << 12) + ((size_t)x << 8) + ((size_t)y << 4) + ((size_t)zq << 2)) * 4;

    #pragma unroll
    for (int t = 0; t < 5; t++) {
        const int  c  = cntc[t];
        const int  cp = cpadc[t];
        const u64 bm = pk2((float)(64 - c) * bxy);
        u64 a0 = mul2(bm, bq.x);
        u64 a1 = mul2(bm, bq.y);

        const char* p = tb + startc[t] * 256;
        for (int k = 0; k < cp; k += 2) {     // even trip count: straight-line 2-wide body
            float sx0 = *(const float*)(p + offx);
            float sy0 = *(const float*)(p + offy);
            ulonglong2 q0 = *(const ulonglong2*)(p + offz);
            float sx1 = *(const float*)(p + 256 + offx);
            float sy1 = *(const float*)(p + 256 + offy);
            ulonglong2 q1 = *(const ulonglong2*)(p + 256 + offz);
            u64 sp0 = pk2(sx0 * sy0);
            u64 sp1 = pk2(sx1 * sy1);
            a0 = fma2(sp0, q0.x, a0);
            a1 = fma2(sp0, q0.y, a1);
            a0 = fma2(sp1, q1.x, a0);
            a1 = fma2(sp1, q1.y, a1);
            p += 512;
        }

        __stcs((ulonglong2*)op, make_ulonglong2(a0, a1));
        op += 2 * 4096 * 4;   // next type channel
    }
}

extern "C" void kernel_launch(void* const* d_in, const int* in_sizes, int n_in,
                              void* d_out, int out_size) {
    const float* dist = nullptr;
    const float* sig  = nullptr;
    const int*   an   = nullptr;
    for (int i = 0; i < n_in; i++) {
        if (in_sizes[i] == 1)          sig  = (const float*)d_in[i];
        else if (in_sizes[i] == 24576) dist = (const float*)d_in[i];
        else if (in_sizes[i] == 8192)  an   = (const int*)d_in[i];
    }
    if (!dist) dist = (const float*)d_in[0];
    if (!sig)  sig  = (const float*)d_in[1];
    if (!an)   an   = (const int*)d_in[2];

    mbv_kernel<<<256, NT>>>(dist, sig, an, (float*)d_out);
}

// round 10
// speedup vs baseline: 1.1754x; 1.1754x over previous
#include <cuda_runtime.h>
#include <cstddef>

// ManyBodyVoxel: out[0, a, c=t*2+l, x, y, z] =
//   sum_n exp(coeff * || grid_l[x,y,z] - d[a,n]*mask_t[a,n] ||^2)
// R10: grid=512 CTAs (a, l, zhalf) x 512 thr (x, y, zq) -> 4:3 balance;
//      Gaussian-row geometric recurrence (center-out) cuts MUFU ~10x;
//      consumer identical to R8 (classified-contiguous 256B records).

#define NT 512

typedef unsigned long long u64;

__device__ __forceinline__ u64 pk2(float v) {
    u64 r; asm("mov.b64 %0, {%1, %2};" : "=l"(r) : "f"(v), "f"(v)); return r;
}
__device__ __forceinline__ u64 fma2(u64 a, u64 b, u64 c) {
    u64 d; asm("fma.rn.f32x2 %0, %1, %2, %3;" : "=l"(d) : "l"(a), "l"(b), "l"(c)); return d;
}
__device__ __forceinline__ u64 mul2(u64 a, u64 b) {
    u64 d; asm("mul.rn.f32x2 %0, %1, %2;" : "=l"(d) : "l"(a), "l"(b)); return d;
}

__global__ __launch_bounds__(NT, 4)
void mbv_kernel(const float* __restrict__ dist,   // (1,128,64,3) fp32
                const float* __restrict__ sigma,  // (1,) fp32
                const int*   __restrict__ anum,   // (128,64) int64 or int32 (auto-detect)
                float* __restrict__ out)          // (1,128,10,16,16,16) fp32
{
    const int b   = blockIdx.x;
    const int a   = b >> 2;
    const int l   = (b >> 1) & 1;    // 0: L=8, 1: L=12
    const int zh  = b & 1;           // z half handled by this CTA
    const int tid = threadIdx.x;
    const int zq  = tid & 1;         // quarter within the half: z = zh*8 + zq*4 + [0,4)
    const int y   = (tid >> 1) & 15;
    const int x   = (tid >> 5) & 15;

    // Record (slot): 64 floats = 256B. x[16] @ +0, y[16] @ +64B, z8[8] @ +128B, pad.
    // Slots 0..ncls-1: classified atoms (type-major compact); slot 64: base (d=0).
    __shared__ __align__(16) float tab[65 * 64];
    __shared__ float dsm[192];
    __shared__ short ord[64];
    __shared__ int   startc[5];
    __shared__ int   cntc[5];
    __shared__ int   nclss;

    const float s  = sigma[0];
    const float cf = -0.5f / (s * s);

    // ---- Phase 0: warp0 classifies (ballot compaction); threads 32..223 stage dist ----
    if (tid < 32) {
        int4 p = ((const int4*)anum)[tid];            // probe row 0 (dtype)
        int4 q = ((const int4*)anum)[a * 32 + tid];   // int64 view
        int2 r = ((const int2*)anum)[a * 32 + tid];   // int32 view
        bool i32 = __any_sync(0xffffffffu, (p.y | p.w) != 0);
        int z0 = i32 ? r.x : q.x;
        int z1 = i32 ? r.y : q.z;
        unsigned lt = (1u << tid) - 1u;
        const int ZT[5] = {1, 6, 7, 8, 16};
        int base = 0;
        #pragma unroll
        for (int t = 0; t < 5; t++) {
            unsigned m0 = __ballot_sync(0xffffffffu, z0 == ZT[t]);
            unsigned m1 = __ballot_sync(0xffffffffu, z1 == ZT[t]);
            int c0 = __popc(m0), c = c0 + __popc(m1);
            if (z0 == ZT[t]) ord[base + __popc(m0 & lt)]      = (short)(2 * tid);
            if (z1 == ZT[t]) ord[base + c0 + __popc(m1 & lt)] = (short)(2 * tid + 1);
            if (tid == 0) { startc[t] = base; cntc[t] = c; }
            base += c;
        }
        if (tid == 0) nclss = base;
    } else if (tid < 224) {
        dsm[tid - 32] = dist[a * 192 + (tid - 32)];
    }

    __syncthreads();

    // ---- Phase 1: exp rows via center-out geometric recurrence ----
    // unit = (slot, axis); ax 0/1 -> 16 ticks, ax 2 -> 8 ticks (this CTA's z half).
    {
        const float Lp   = l ? 12.0f : 8.0f;
        const float half = 0.5f * Lp;
        const float step = Lp * (1.0f / 15.0f);
        const float Brat = __expf(2.0f * cf * step * step);  // uniform per CTA

        const int nrec = nclss + 1;
        if (tid < 3 * nrec) {
            int slot = tid / 3;
            int ax   = tid - slot * 3;
            int isbase = (slot == nclss);
            int recid  = isbase ? 64 : slot;
            float dv   = isbase ? 0.0f : dsm[(int)ord[slot] * 3 + ax];
            float* dst = &tab[recid * 64 + ax * 16];   // z8 row sits at +128B = idx 32
            int j0 = 0, m = 16;
            if (ax == 2) { dst = &tab[recid * 64 + 32]; j0 = zh * 8; m = 8; }

            float bse = -half - dv;
            // center tick (peak of the Gaussian) clamped into [j0, j0+m-1]
            int jc = __float2int_rn(-bse / step);
            jc = max(j0, min(j0 + m - 1, jc));
            float uc = bse + step * (float)jc;
            float fc = __expf(cf * uc * uc);
            float ru = __expf(cf * step * (2.0f * uc + step));   // ratio toward j+1
            float rd = __expf(cf * step * (step - 2.0f * uc));   // ratio toward j-1
            dst[jc - j0] = fc;
            float f = fc, r = ru;
            for (int j = jc + 1; j < j0 + m; j++) { f *= r; r *= Brat; dst[j - j0] = f; }
            f = fc; r = rd;
            for (int j = jc - 1; j >= j0; j--)    { f *= r; r *= Brat; dst[j - j0] = f; }
        }
    }

    __syncthreads();

    // ---- Phase 2: consumer (R8 loop). Thread owns 4 voxels z=zh*8+zq*4+[0,4) ----
    const char* tb = reinterpret_cast<const char*>(tab);
    const int offx = x * 4;
    const int offy = 64 + y * 4;
    const int offz = 128 + zq * 16;

    const char* br = tb + 64 * 256;   // base record
    const float bxy = *(const float*)(br + offx) * *(const float*)(br + offy);
    const ulonglong2 bq = *(const ulonglong2*)(br + offz);

    // out offset (floats): (a*10 + t*2 + l)*4096 + x*256 + y*16 + zh*8 + zq*4
    char* op = reinterpret_cast<char*>(out)
             + ((((size_t)(a * 10 + l)) << 12) + ((size_t)x << 8) + ((size_t)y << 4)
                + ((size_t)zh << 3) + ((size_t)zq << 2)) * 4;

    #pragma unroll
    for (int t = 0; t < 5; t++) {
        const int c  = cntc[t];
        const u64 bm = pk2((float)(64 - c) * bxy);
        u64 a0 = mul2(bm, bq.x);
        u64 a1 = mul2(bm, bq.y);

        const char* p = tb + startc[t] * 256;
        #pragma unroll 2
        for (int k = 0; k < c; k++) {
            float sx = *(const float*)(p + offx);
            float sy = *(const float*)(p + offy);
            ulonglong2 q = *(const ulonglong2*)(p + offz);
            u64 sp = pk2(sx * sy);
            a0 = fma2(sp, q.x, a0);
            a1 = fma2(sp, q.y, a1);
            p += 256;
        }

        __stcs((ulonglong2*)op, make_ulonglong2(a0, a1));
        op += 2 * 4096 * 4;   // next type channel
    }
}

extern "C" void kernel_launch(void* const* d_in, const int* in_sizes, int n_in,
                              void* d_out, int out_size) {
    const float* dist = nullptr;
    const float* sig  = nullptr;
    const int*   an   = nullptr;
    for (int i = 0; i < n_in; i++) {
        if (in_sizes[i] == 1)          sig  = (const float*)d_in[i];
        else if (in_sizes[i] == 24576) dist = (const float*)d_in[i];
        else if (in_sizes[i] == 8192)  an   = (const int*)d_in[i];
    }
    if (!dist) dist = (const float*)d_in[0];
    if (!sig)  sig  = (const float*)d_in[1];
    if (!an)   an   = (const int*)d_in[2];

    mbv_kernel<<<512, NT>>>(dist, sig, an, (float*)d_out);
}